// round 4
// baseline (speedup 1.0000x reference)
#include <cuda_runtime.h>
#include <cuda_bf16.h>

// ---------------------------------------------------------------------------
// Net_58712202936903: 2-layer multiplicative net + JVP, restructured as a
// 45x45 quadratic form in the 8-dim input monomial basis.
//
//   m(x) = (1, x_i, x_i x_j for i<=j)            (45 terms)
//   out(x)      = 0.5 * m . (Ssym m)
//   grad(x,xd)  = dm . (Ssym m)
// where Ssym is precomputed per-launch from the weights.
// ---------------------------------------------------------------------------

#define N_IN   8
#define H1     128
#define H2     128
#define NMON   45      // 1 + 8 + 36
#define SPAD   48      // padded row stride for Ssym / A1 / A2
#define NPAIR  36

#define ROWS_T 65536
#define ROWS_L 65536
#define ROWS_C 512
#define ROWS_TOTAL (ROWS_T + ROWS_L + ROWS_C)   // 131584 = 514*256

// pair index -> (i,j), i<=j, row-major upper triangle
static __device__ __constant__ int c_PI[NPAIR] =
  {0,0,0,0,0,0,0,0, 1,1,1,1,1,1,1, 2,2,2,2,2,2, 3,3,3,3,3, 4,4,4,4, 5,5,5, 6,6, 7};
static __device__ __constant__ int c_PJ[NPAIR] =
  {0,1,2,3,4,5,6,7, 1,2,3,4,5,6,7, 2,3,4,5,6,7, 3,4,5,6,7, 4,5,6,7, 5,6,7, 6,7, 7};

// scratch (device globals: allowed; zero-initialized)
__device__ float gQ [H1 * NMON];   // layer-1 quadratic coefficients
__device__ float gA1[H2 * SPAD];   // W1_2 @ Q (+ b1_2 on monomial 0)
__device__ float gA2[H2 * SPAD];   // W2_2 @ Q (+ b2_2 on monomial 0)
__device__ float gS [NMON * SPAD]; // Ssym, padded rows (pad cols stay 0)

// ---------------------------------------------------------------------------
// P1: per-hidden-unit quadratic coefficients of y_o(x) = z1_o(x) * z2_o(x)
// ---------------------------------------------------------------------------
__global__ void kQ(const float* __restrict__ w1, const float* __restrict__ b1,
                   const float* __restrict__ w2, const float* __restrict__ b2) {
    int h = threadIdx.x;            // 0..127
    float a[N_IN], c[N_IN];
#pragma unroll
    for (int i = 0; i < N_IN; i++) { a[i] = w1[h * N_IN + i]; c[i] = w2[h * N_IN + i]; }
    float bb1 = b1[h], bb2 = b2[h];
    float* q = gQ + h * NMON;
    q[0] = bb1 * bb2;
#pragma unroll
    for (int i = 0; i < N_IN; i++) q[1 + i] = fmaf(bb1, c[i], bb2 * a[i]);
#pragma unroll
    for (int t = 0; t < NPAIR; t++) {
        int i = c_PI[t], j = c_PJ[t];
        q[9 + t] = (i == j) ? a[i] * c[i] : fmaf(a[i], c[j], a[j] * c[i]);
    }
}

// ---------------------------------------------------------------------------
// P2: A1 = W1_2 @ Q (+b1_2 e0), A2 = W2_2 @ Q (+b2_2 e0).  grid = 45 (p), 128 thr (h)
// ---------------------------------------------------------------------------
__global__ void kA(const float* __restrict__ w1, const float* __restrict__ b1,
                   const float* __restrict__ w2, const float* __restrict__ b2) {
    int p = blockIdx.x;             // monomial 0..44
    int h = threadIdx.x;            // 0..127
    __shared__ float sQ[H1];
    sQ[h] = gQ[h * NMON + p];
    __syncthreads();
    float a1 = 0.f, a2 = 0.f;
#pragma unroll 8
    for (int o = 0; o < H1; o++) {
        float qv = sQ[o];
        a1 = fmaf(w1[h * H1 + o], qv, a1);
        a2 = fmaf(w2[h * H1 + o], qv, a2);
    }
    if (p == 0) { a1 += b1[h]; a2 += b2[h]; }
    gA1[h * SPAD + p] = a1;
    gA2[h * SPAD + p] = a2;
}

// ---------------------------------------------------------------------------
// P3: Ssym[p][q] = sum_h w[h] * (A1[h,p]A2[h,q] + A1[h,q]A2[h,p])
// ---------------------------------------------------------------------------
__global__ void kS(const float* __restrict__ w_out) {
    int idx = blockIdx.x * blockDim.x + threadIdx.x;
    if (idx >= NMON * NMON) return;
    int p = idx / NMON, q = idx % NMON;
    float s = 0.f;
#pragma unroll 4
    for (int h = 0; h < H2; h++) {
        float wv  = __ldg(w_out + h);
        float a1p = __ldg(gA1 + h * SPAD + p);
        float a2q = __ldg(gA2 + h * SPAD + q);
        float a1q = __ldg(gA1 + h * SPAD + q);
        float a2p = __ldg(gA2 + h * SPAD + p);
        s = fmaf(wv, fmaf(a1p, a2q, a1q * a2p), s);
    }
    gS[p * SPAD + q] = s;
}

// ---------------------------------------------------------------------------
// Main: one thread per row.  Ssym in smem (uniform broadcast reads).
// ---------------------------------------------------------------------------
__global__ void __launch_bounds__(256)
kMain(const float* __restrict__ T, const float* __restrict__ L,
      const float* __restrict__ Ld, const float* __restrict__ C,
      float* __restrict__ out) {
    __shared__ float sS[NMON * SPAD];
    for (int i = threadIdx.x; i < NMON * SPAD; i += 256) sS[i] = gS[i];
    __syncthreads();

    int r = blockIdx.x * 256 + threadIdx.x;   // grid sized exactly ROWS_TOTAL

    float x[N_IN], xd[N_IN];
    int dsto, dstg = -1;
    if (r < ROWS_T) {
        const float4* p4 = reinterpret_cast<const float4*>(T + r * N_IN);
        float4 a = p4[0], b = p4[1];
        x[0]=a.x; x[1]=a.y; x[2]=a.z; x[3]=a.w; x[4]=b.x; x[5]=b.y; x[6]=b.z; x[7]=b.w;
#pragma unroll
        for (int i = 0; i < N_IN; i++) xd[i] = 0.f;
        dsto = r;
    } else if (r < ROWS_T + ROWS_L) {
        int i = r - ROWS_T;
        const float4* p4 = reinterpret_cast<const float4*>(L + i * N_IN);
        float4 a = p4[0], b = p4[1];
        x[0]=a.x; x[1]=a.y; x[2]=a.z; x[3]=a.w; x[4]=b.x; x[5]=b.y; x[6]=b.z; x[7]=b.w;
        const float4* d4 = reinterpret_cast<const float4*>(Ld + i * N_IN);
        float4 c = d4[0], d = d4[1];
        xd[0]=c.x; xd[1]=c.y; xd[2]=c.z; xd[3]=c.w; xd[4]=d.x; xd[5]=d.y; xd[6]=d.z; xd[7]=d.w;
        dsto = ROWS_T + i;              // v_y
        dstg = 2 * ROWS_T + i;          // v_grad
    } else {
        int i = r - (ROWS_T + ROWS_L);
        const float4* p4 = reinterpret_cast<const float4*>(C + i * N_IN);
        float4 a = p4[0], b = p4[1];
        x[0]=a.x; x[1]=a.y; x[2]=a.z; x[3]=a.w; x[4]=b.x; x[5]=b.y; x[6]=b.z; x[7]=b.w;
#pragma unroll
        for (int i2 = 0; i2 < N_IN; i2++) xd[i2] = 0.f;
        dsto = 3 * ROWS_T + i;          // v_center
    }

    // monomial vector
    float m[NMON];
    m[0] = 1.f;
#pragma unroll
    for (int i = 0; i < N_IN; i++) m[1 + i] = x[i];
#pragma unroll
    for (int t = 0; t < NPAIR; t++) m[9 + t] = x[c_PI[t]] * x[c_PJ[t]];

    float acc_o = 0.f, acc_g = 0.f;
#pragma unroll
    for (int p = 0; p < NMON; p++) {
        const float* row = sS + p * SPAD;
        float v0 = 0.f, v1 = 0.f, v2 = 0.f, v3 = 0.f;
#pragma unroll
        for (int q = 0; q < 44; q += 4) {
            v0 = fmaf(row[q],     m[q],     v0);
            v1 = fmaf(row[q + 1], m[q + 1], v1);
            v2 = fmaf(row[q + 2], m[q + 2], v2);
            v3 = fmaf(row[q + 3], m[q + 3], v3);
        }
        float v = ((v0 + v1) + (v2 + v3)) + row[44] * m[44];
        acc_o = fmaf(m[p], v, acc_o);
        if (p >= 1) {
            float dmp;
            if (p < 9) {
                dmp = xd[p - 1];
            } else {
                int i = c_PI[p - 9], j = c_PJ[p - 9];
                dmp = fmaf(x[i], xd[j], x[j] * xd[i]);   // handles i==j (2*x*xd)
            }
            acc_g = fmaf(dmp, v, acc_g);
        }
    }

    out[dsto] = 0.5f * acc_o;
    if (dstg >= 0) out[dstg] = acc_g;
}

// ---------------------------------------------------------------------------
extern "C" void kernel_launch(void* const* d_in, const int* in_sizes, int n_in,
                              void* d_out, int out_size) {
    const float* T     = (const float*)d_in[0];
    const float* l     = (const float*)d_in[1];
    const float* ldot  = (const float*)d_in[2];
    const float* center= (const float*)d_in[3];
    const float* w1_1  = (const float*)d_in[4];
    const float* b1_1  = (const float*)d_in[5];
    const float* w2_1  = (const float*)d_in[6];
    const float* b2_1  = (const float*)d_in[7];
    const float* w1_2  = (const float*)d_in[8];
    const float* b1_2  = (const float*)d_in[9];
    const float* w2_2  = (const float*)d_in[10];
    const float* b2_2  = (const float*)d_in[11];
    const float* w_out = (const float*)d_in[12];
    float* out = (float*)d_out;

    kQ<<<1, H1>>>(w1_1, b1_1, w2_1, b2_1);
    kA<<<NMON, H1>>>(w1_2, b1_2, w2_2, b2_2);
    kS<<<(NMON * NMON + 255) / 256, 256>>>(w_out);
    kMain<<<ROWS_TOTAL / 256, 256>>>(T, l, ldot, center, out);
}

// round 9
// speedup vs baseline: 2.2059x; 2.2059x over previous
#include <cuda_runtime.h>
#include <cuda_bf16.h>

// ---------------------------------------------------------------------------
// Net_58712202936903: 2-layer multiplicative net + JVP as a 45x45 quadratic
// form in the 8-dim input monomial basis m(x) = (1, x_i, x_i x_j | i<=j).
//   out(x)     = 0.5 * m . (Ssym m)
//   grad(x,xd) = (J_m^T (Ssym m)) . xd
// ---------------------------------------------------------------------------

#define N_IN   8
#define H1     128
#define H2     128
#define NMON   45
#define SPAD   48      // padded row stride (12 float4)
#define NPAIR  36
#define QSTR   64      // Q smem row stride

#define ROWS_T 65536
#define ROWS_L 65536
#define ROWS_C 512
#define ROWS_TOTAL (ROWS_T + ROWS_L + ROWS_C)   // 131584 = 514*256

// pair index t -> (i,j), i<=j, row-major upper triangle of 8x8.
// constexpr FUNCTIONS (not arrays) so they are valid in device code and fold
// to immediates when called with compile-time t inside fully unrolled loops.
__host__ __device__ constexpr int pair_i(int t) {
    int i = 0, off = 0;
    while (t >= off + (N_IN - i)) { off += N_IN - i; ++i; }
    return i;
}
__host__ __device__ constexpr int pair_j(int t) {
    int i = 0, off = 0;
    while (t >= off + (N_IN - i)) { off += N_IN - i; ++i; }
    return i + (t - off);
}

// device scratch (zero-initialized; pad columns of gS are never written -> stay 0)
__device__ float gA1[H2 * SPAD];
__device__ float gA2[H2 * SPAD];
__device__ float gS [NMON * SPAD];

// ---------------------------------------------------------------------------
// Prep 1: Q (per-block smem) -> A1 = W1_2 Q (+b1_2 e0), A2 = W2_2 Q (+b2_2 e0)
// grid = 16 blocks x 256 threads; warp w of block b owns hidden unit h = b*8+w.
// Uniform W reads (broadcast), coalesced smem Q-column reads.
// ---------------------------------------------------------------------------
__global__ void __launch_bounds__(256)
kPrepQA(const float* __restrict__ w1_1, const float* __restrict__ b1_1,
        const float* __restrict__ w2_1, const float* __restrict__ b2_1,
        const float* __restrict__ w1_2, const float* __restrict__ b1_2,
        const float* __restrict__ w2_2, const float* __restrict__ b2_2) {
    __shared__ float sQ[H1 * QSTR];   // 32 KB
    int tid = threadIdx.x;

    // Phase 1: threads 0..127 each build one Q row (layer-1 quadratic coeffs)
    if (tid < H1) {
        int h = tid;
        float a[N_IN], c[N_IN];
#pragma unroll
        for (int i = 0; i < N_IN; i++) { a[i] = w1_1[h*N_IN+i]; c[i] = w2_1[h*N_IN+i]; }
        float bb1 = b1_1[h], bb2 = b2_1[h];
        float* q = sQ + h * QSTR;
        q[0] = bb1 * bb2;
#pragma unroll
        for (int i = 0; i < N_IN; i++) q[1+i] = fmaf(bb1, c[i], bb2 * a[i]);
#pragma unroll
        for (int t = 0; t < NPAIR; t++) {
            constexpr int dummy = 0; (void)dummy;
            int i = pair_i(t), j = pair_j(t);
            q[9+t] = (i == j) ? a[i]*c[i] : fmaf(a[i], c[j], a[j]*c[i]);
        }
#pragma unroll
        for (int t = NMON; t < QSTR; t++) q[t] = 0.f;
    }
    __syncthreads();

    // Phase 2: warp -> h; lanes cover p (lane) and p+32
    int warp = tid >> 5, lane = tid & 31;
    int h = blockIdx.x * 8 + warp;
    const float* W1 = w1_2 + h * H1;
    const float* W2 = w2_2 + h * H1;
    float a10 = 0.f, a11 = 0.f, a20 = 0.f, a21 = 0.f;
#pragma unroll 8
    for (int o = 0; o < H1; o++) {
        float wv1 = W1[o], wv2 = W2[o];         // uniform -> broadcast
        float q0 = sQ[o * QSTR + lane];
        float q1 = sQ[o * QSTR + lane + 32];    // zero-padded -> safe
        a10 = fmaf(wv1, q0, a10);  a11 = fmaf(wv1, q1, a11);
        a20 = fmaf(wv2, q0, a20);  a21 = fmaf(wv2, q1, a21);
    }
    if (lane == 0) { a10 += b1_2[h]; a20 += b2_2[h]; }
    gA1[h * SPAD + lane] = a10;
    gA2[h * SPAD + lane] = a20;
    if (lane + 32 < NMON) {
        gA1[h * SPAD + lane + 32] = a11;
        gA2[h * SPAD + lane + 32] = a21;
    }
}

// ---------------------------------------------------------------------------
// Prep 2: Ssym[p][q] = sum_h w[h]*(A1[h,p]A2[h,q] + A1[h,q]A2[h,p])
// grid = 45 blocks (p) x 64 threads (q). Stage u1=w*A1[:,p], u2=w*A2[:,p].
// q-reads of gA are consecutive across lanes (coalesced).
// ---------------------------------------------------------------------------
__global__ void __launch_bounds__(64)
kS(const float* __restrict__ w_out) {
    int p = blockIdx.x;
    int tid = threadIdx.x;
    __shared__ float su1[H2], su2[H2];
    for (int h = tid; h < H2; h += 64) {
        float w = w_out[h];
        su1[h] = w * gA1[h * SPAD + p];
        su2[h] = w * gA2[h * SPAD + p];
    }
    __syncthreads();
    if (tid < NMON) {
        int q = tid;
        float s0 = 0.f, s1 = 0.f, s2 = 0.f, s3 = 0.f;
#pragma unroll 8
        for (int h = 0; h < H2; h += 4) {
            s0 = fmaf(su1[h+0], gA2[(h+0)*SPAD+q], fmaf(su2[h+0], gA1[(h+0)*SPAD+q], s0));
            s1 = fmaf(su1[h+1], gA2[(h+1)*SPAD+q], fmaf(su2[h+1], gA1[(h+1)*SPAD+q], s1));
            s2 = fmaf(su1[h+2], gA2[(h+2)*SPAD+q], fmaf(su2[h+2], gA1[(h+2)*SPAD+q], s2));
            s3 = fmaf(su1[h+3], gA2[(h+3)*SPAD+q], fmaf(su2[h+3], gA1[(h+3)*SPAD+q], s3));
        }
        gS[p * SPAD + q] = (s0 + s1) + (s2 + s3);
    }
}

// ---------------------------------------------------------------------------
// Main: one thread per row. Ssym in smem, float4 broadcast reads.
// ---------------------------------------------------------------------------
__global__ void __launch_bounds__(256, 2)
kMain(const float* __restrict__ T, const float* __restrict__ L,
      const float* __restrict__ Ld, const float* __restrict__ C,
      float* __restrict__ out) {
    __shared__ float sS[NMON * SPAD];   // 8640 B
    for (int i = threadIdx.x; i < NMON * SPAD; i += 256) sS[i] = gS[i];
    __syncthreads();

    int r = blockIdx.x * 256 + threadIdx.x;   // grid exactly covers ROWS_TOTAL

    float x[N_IN];
    int dsto, dstg = -1;
    const float* src;
    if (r < ROWS_T) {                       // blocks 0..255 (uniform branch)
        src = T + (size_t)r * N_IN;
        dsto = r;
    } else if (r < ROWS_T + ROWS_L) {       // blocks 256..511 (uniform)
        int i = r - ROWS_T;
        src = L + (size_t)i * N_IN;
        dsto = ROWS_T + i;                  // v_y
        dstg = 2 * ROWS_T + i;              // v_grad
    } else {                                // blocks 512..513 (uniform)
        int i = r - (ROWS_T + ROWS_L);
        src = C + (size_t)i * N_IN;
        dsto = 3 * ROWS_T + i;              // v_center
    }
    {
        const float4* p4 = reinterpret_cast<const float4*>(src);
        float4 a = p4[0], b = p4[1];
        x[0]=a.x; x[1]=a.y; x[2]=a.z; x[3]=a.w;
        x[4]=b.x; x[5]=b.y; x[6]=b.z; x[7]=b.w;
    }

    // monomial vector, padded to 48
    float m[SPAD];
    m[0] = 1.f;
#pragma unroll
    for (int i = 0; i < N_IN; i++) m[1+i] = x[i];
#pragma unroll
    for (int t = 0; t < NPAIR; t++) m[9+t] = x[pair_i(t)] * x[pair_j(t)];
    m[45] = 0.f; m[46] = 0.f; m[47] = 0.f;

    float acc_o = 0.f;
    float g[N_IN];
#pragma unroll
    for (int i = 0; i < N_IN; i++) g[i] = 0.f;

#pragma unroll
    for (int p = 0; p < NMON; p++) {
        const float4* row4 = reinterpret_cast<const float4*>(sS + p * SPAD);
        float v0 = 0.f, v1 = 0.f, v2 = 0.f, v3 = 0.f;
#pragma unroll
        for (int qq = 0; qq < 12; qq++) {
            float4 rv = row4[qq];               // uniform LDS.128 (broadcast)
            v0 = fmaf(rv.x, m[4*qq+0], v0);
            v1 = fmaf(rv.y, m[4*qq+1], v1);
            v2 = fmaf(rv.z, m[4*qq+2], v2);
            v3 = fmaf(rv.w, m[4*qq+3], v3);
        }
        float v = (v0 + v1) + (v2 + v3);        // v_p = (Ssym m)_p
        acc_o = fmaf(m[p], v, acc_o);
        // g = J_m(x)^T v, all indices compile-time
        if (p >= 1 && p < 9) {
            g[p-1] += v;
        } else if (p >= 9) {
            int i = pair_i(p - 9), j = pair_j(p - 9);
            g[i] = fmaf(v, x[j], g[i]);
            g[j] = fmaf(v, x[i], g[j]);         // i==j double-add = 2 x_i v (correct)
        }
    }

    out[dsto] = 0.5f * acc_o;
    if (dstg >= 0) {
        int i = r - ROWS_T;
        const float4* d4 = reinterpret_cast<const float4*>(Ld + (size_t)i * N_IN);
        float4 a = d4[0], b = d4[1];
        float ag = 0.f;
        ag = fmaf(g[0], a.x, ag); ag = fmaf(g[1], a.y, ag);
        ag = fmaf(g[2], a.z, ag); ag = fmaf(g[3], a.w, ag);
        ag = fmaf(g[4], b.x, ag); ag = fmaf(g[5], b.y, ag);
        ag = fmaf(g[6], b.z, ag); ag = fmaf(g[7], b.w, ag);
        out[dstg] = ag;
    }
}

// ---------------------------------------------------------------------------
extern "C" void kernel_launch(void* const* d_in, const int* in_sizes, int n_in,
                              void* d_out, int out_size) {
    const float* T      = (const float*)d_in[0];
    const float* l      = (const float*)d_in[1];
    const float* ldot   = (const float*)d_in[2];
    const float* center = (const float*)d_in[3];
    const float* w1_1   = (const float*)d_in[4];
    const float* b1_1   = (const float*)d_in[5];
    const float* w2_1   = (const float*)d_in[6];
    const float* b2_1   = (const float*)d_in[7];
    const float* w1_2   = (const float*)d_in[8];
    const float* b1_2   = (const float*)d_in[9];
    const float* w2_2   = (const float*)d_in[10];
    const float* b2_2   = (const float*)d_in[11];
    const float* w_out  = (const float*)d_in[12];
    float* out = (float*)d_out;

    kPrepQA<<<16, 256>>>(w1_1, b1_1, w2_1, b2_1, w1_2, b1_2, w2_2, b2_2);
    kS<<<NMON, 64>>>(w_out);
    kMain<<<ROWS_TOTAL / 256, 256>>>(T, l, ldot, center, out);
}

// round 11
// speedup vs baseline: 2.4169x; 1.0957x over previous
#include <cuda_runtime.h>
#include <cuda_bf16.h>
#include <cstdint>

// ---------------------------------------------------------------------------
// Net_58712202936903: 2-layer multiplicative net + JVP as a 45x45 quadratic
// form in the 8-dim monomial basis m(x) = (1, x_i, x_i x_j | i<=j).
//   out(x)     = 0.5 * m . (Ssym m)
//   grad(x,xd) = (J_m^T (Ssym m)) . xd
// kMain uses packed f32x2 FMA (FFMA2) for the 45x48 matvec.
// ---------------------------------------------------------------------------

#define N_IN   8
#define H1     128
#define H2     128
#define NMON   45
#define SPAD   48      // padded row stride (12 float4)
#define NPAIR  36
#define QSTR   64      // Q smem row stride

#define ROWS_T 65536
#define ROWS_L 65536
#define ROWS_C 512
#define ROWS_TOTAL (ROWS_T + ROWS_L + ROWS_C)   // 131584 = 514*256

// pair index t -> (i,j), i<=j, row-major upper triangle of 8x8 (constexpr fns
// fold to immediates inside fully unrolled loops; valid in device code).
__host__ __device__ constexpr int pair_i(int t) {
    int i = 0, off = 0;
    while (t >= off + (N_IN - i)) { off += N_IN - i; ++i; }
    return i;
}
__host__ __device__ constexpr int pair_j(int t) {
    int i = 0, off = 0;
    while (t >= off + (N_IN - i)) { off += N_IN - i; ++i; }
    return i + (t - off);
}

// device scratch (zero-initialized; pad entries never written -> stay 0)
__device__ float gA1[H2 * SPAD];
__device__ float gA2[H2 * SPAD];
__device__ float gS [NMON * SPAD];

// ---- packed f32x2 helpers --------------------------------------------------
__device__ __forceinline__ uint32_t smem_u32(const void* p) {
    uint32_t a;
    asm("{ .reg .u64 t; cvta.to.shared.u64 t, %1; cvt.u32.u64 %0, t; }"
        : "=r"(a) : "l"(p));
    return a;
}
#define FMA2(acc, a, b) \
    asm("fma.rn.f32x2 %0, %1, %2, %0;" : "+l"(acc) : "l"(a), "l"(b))
#define ADD2(d, a, b) \
    asm("add.rn.f32x2 %0, %1, %2;" : "=l"(d) : "l"(a), "l"(b))
#define PACK2(d, lo, hi) \
    asm("mov.b64 %0, {%1, %2};" : "=l"(d) : "f"(lo), "f"(hi))
#define UNPACK2(lo, hi, s) \
    asm("mov.b64 {%0, %1}, %2;" : "=f"(lo), "=f"(hi) : "l"(s))
#define LDS_V2B64(a, b, addr) \
    asm volatile("ld.shared.v2.b64 {%0, %1}, [%2];" \
                 : "=l"(a), "=l"(b) : "r"(addr))

// ---------------------------------------------------------------------------
// Prep 1: one block per hidden unit h of layer 2.
//   Phase 1: all 128 threads build full Q (layer-1 quadratic coeffs) in smem
//            (redundant across blocks; trivially cheap).
//   Phase 2: threads split the o-dim in halves (depth 64), smem combine.
// A1 = W1_2 Q (+b1_2 e0), A2 = W2_2 Q (+b2_2 e0).
// ---------------------------------------------------------------------------
__global__ void __launch_bounds__(128)
kPrepQA(const float* __restrict__ w1_1, const float* __restrict__ b1_1,
        const float* __restrict__ w2_1, const float* __restrict__ b2_1,
        const float* __restrict__ w1_2, const float* __restrict__ b1_2,
        const float* __restrict__ w2_2, const float* __restrict__ b2_2) {
    __shared__ float sQ[H1 * QSTR];          // 32 KB
    __shared__ float sW1[H1], sW2[H1];
    __shared__ float pA1[2][QSTR], pA2[2][QSTR];
    int tid = threadIdx.x;
    int h   = blockIdx.x;                    // 0..127

    // Phase 1: thread t builds Q row t
    {
        int hr = tid;
        float a[N_IN], c[N_IN];
#pragma unroll
        for (int i = 0; i < N_IN; i++) { a[i] = w1_1[hr*N_IN+i]; c[i] = w2_1[hr*N_IN+i]; }
        float bb1 = b1_1[hr], bb2 = b2_1[hr];
        float* q = sQ + hr * QSTR;
        q[0] = bb1 * bb2;
#pragma unroll
        for (int i = 0; i < N_IN; i++) q[1+i] = fmaf(bb1, c[i], bb2 * a[i]);
#pragma unroll
        for (int t = 0; t < NPAIR; t++) {
            int i = pair_i(t), j = pair_j(t);
            q[9+t] = (i == j) ? a[i]*c[i] : fmaf(a[i], c[j], a[j]*c[i]);
        }
#pragma unroll
        for (int t = NMON; t < QSTR; t++) q[t] = 0.f;
        // stage this block's W rows (coalesced)
        sW1[tid] = w1_2[h * H1 + tid];
        sW2[tid] = w2_2[h * H1 + tid];
    }
    __syncthreads();

    // Phase 2: half = o-range, p = column
    int half = tid >> 6;                     // 0 or 1
    int p    = tid & 63;
    int obase = half * 64;
    float a1 = 0.f, a2 = 0.f;
#pragma unroll 8
    for (int oo = 0; oo < 64; oo++) {
        int o = obase + oo;
        float q = sQ[o * QSTR + p];
        a1 = fmaf(sW1[o], q, a1);
        a2 = fmaf(sW2[o], q, a2);
    }
    pA1[half][p] = a1;
    pA2[half][p] = a2;
    __syncthreads();
    if (tid < NMON) {
        float r1 = pA1[0][tid] + pA1[1][tid];
        float r2 = pA2[0][tid] + pA2[1][tid];
        if (tid == 0) { r1 += b1_2[h]; r2 += b2_2[h]; }
        gA1[h * SPAD + tid] = r1;
        gA2[h * SPAD + tid] = r2;
    }
}

// ---------------------------------------------------------------------------
// Prep 2: Ssym[p][q] = sum_h w[h]*(A1[h,p]A2[h,q] + A1[h,q]A2[h,p])
// grid = 45 blocks (p) x 256 threads (64 q-lanes x 4 h-chunks of 32).
// gA pad columns are zero (never written), so q up to 63 reads are safe.
// ---------------------------------------------------------------------------
__global__ void __launch_bounds__(256)
kS(const float* __restrict__ w_out) {
    int p   = blockIdx.x;
    int tid = threadIdx.x;
    int hc  = tid >> 6;          // 0..3
    int q   = tid & 63;
    __shared__ float su1[H2], su2[H2];
    __shared__ float sp[4][QSTR];
    if (tid < H2) {
        float w = w_out[tid];
        su1[tid] = w * gA1[tid * SPAD + p];
        su2[tid] = w * gA2[tid * SPAD + p];
    }
    __syncthreads();
    float s0 = 0.f, s1 = 0.f;
    int hb = hc * 32;
#pragma unroll 8
    for (int hh = 0; hh < 32; hh += 2) {
        int h = hb + hh;
        s0 = fmaf(su1[h  ], gA2[(h  )*SPAD+q], fmaf(su2[h  ], gA1[(h  )*SPAD+q], s0));
        s1 = fmaf(su1[h+1], gA2[(h+1)*SPAD+q], fmaf(su2[h+1], gA1[(h+1)*SPAD+q], s1));
    }
    sp[hc][q] = s0 + s1;
    __syncthreads();
    if (tid < NMON)
        gS[p * SPAD + tid] = (sp[0][tid] + sp[1][tid]) + (sp[2][tid] + sp[3][tid]);
}

// ---------------------------------------------------------------------------
// Main: one thread per row. Ssym in smem; packed f32x2 matvec.
// ---------------------------------------------------------------------------
__global__ void __launch_bounds__(256, 2)
kMain(const float* __restrict__ T, const float* __restrict__ L,
      const float* __restrict__ Ld, const float* __restrict__ C,
      float* __restrict__ out) {
    __shared__ __align__(16) float sS[NMON * SPAD];   // 8640 B
    for (int i = threadIdx.x; i < NMON * SPAD; i += 256) sS[i] = gS[i];
    __syncthreads();
    uint32_t sbase = smem_u32(sS);

    int r = blockIdx.x * 256 + threadIdx.x;   // grid exactly covers ROWS_TOTAL

    float x[N_IN];
    int dsto, dstg = -1;
    const float* src;
    if (r < ROWS_T) {                        // blocks 0..255 (uniform branch)
        src = T + (size_t)r * N_IN;
        dsto = r;
    } else if (r < ROWS_T + ROWS_L) {        // blocks 256..511 (uniform)
        int i = r - ROWS_T;
        src = L + (size_t)i * N_IN;
        dsto = ROWS_T + i;                   // v_y
        dstg = 2 * ROWS_T + i;               // v_grad
    } else {                                 // blocks 512..513 (uniform)
        int i = r - (ROWS_T + ROWS_L);
        src = C + (size_t)i * N_IN;
        dsto = 3 * ROWS_T + i;               // v_center
    }
    {
        const float4* p4 = reinterpret_cast<const float4*>(src);
        float4 a = p4[0], b = p4[1];
        x[0]=a.x; x[1]=a.y; x[2]=a.z; x[3]=a.w;
        x[4]=b.x; x[5]=b.y; x[6]=b.z; x[7]=b.w;
    }

    // monomial vector (temps), then pack into 24 f32x2 pairs
    float m[SPAD];
    m[0] = 1.f;
#pragma unroll
    for (int i = 0; i < N_IN; i++) m[1+i] = x[i];
#pragma unroll
    for (int t = 0; t < NPAIR; t++) m[9+t] = x[pair_i(t)] * x[pair_j(t)];
    m[45] = 0.f; m[46] = 0.f; m[47] = 0.f;
    unsigned long long mm[24];
#pragma unroll
    for (int k = 0; k < 24; k++) PACK2(mm[k], m[2*k], m[2*k+1]);

    float acc_o = 0.f;
    float g[N_IN];
#pragma unroll
    for (int i = 0; i < N_IN; i++) g[i] = 0.f;

#pragma unroll
    for (int p = 0; p < NMON; p++) {
        unsigned long long a0 = 0ull, a1 = 0ull, a2 = 0ull, a3 = 0ull;
#pragma unroll
        for (int qq = 0; qq < 12; qq += 2) {
            unsigned long long ra, rb, rc, rd;
            LDS_V2B64(ra, rb, sbase + (uint32_t)((p * SPAD + qq * 4) * 4));
            LDS_V2B64(rc, rd, sbase + (uint32_t)((p * SPAD + qq * 4 + 4) * 4));
            FMA2(a0, ra, mm[2*qq+0]);
            FMA2(a1, rb, mm[2*qq+1]);
            FMA2(a2, rc, mm[2*qq+2]);
            FMA2(a3, rd, mm[2*qq+3]);
        }
        unsigned long long t0, t1, tt;
        ADD2(t0, a0, a1);
        ADD2(t1, a2, a3);
        ADD2(tt, t0, t1);
        float va, vb;
        UNPACK2(va, vb, tt);
        float v = va + vb;                    // v_p = (Ssym m)_p
        // value accumulation: multiplier m_p recomputed (keeps m[] dead)
        if (p == 0) {
            acc_o += v;
        } else if (p < 9) {
            acc_o = fmaf(x[p-1], v, acc_o);
            g[p-1] += v;
        } else {
            int i = pair_i(p - 9), j = pair_j(p - 9);
            acc_o = fmaf(x[i] * x[j], v, acc_o);
            g[i] = fmaf(v, x[j], g[i]);
            g[j] = fmaf(v, x[i], g[j]);       // i==j double-add = 2 x_i v (correct)
        }
    }

    out[dsto] = 0.5f * acc_o;
    if (dstg >= 0) {
        int i = r - ROWS_T;
        const float4* d4 = reinterpret_cast<const float4*>(Ld + (size_t)i * N_IN);
        float4 a = d4[0], b = d4[1];
        float ag = 0.f;
        ag = fmaf(g[0], a.x, ag); ag = fmaf(g[1], a.y, ag);
        ag = fmaf(g[2], a.z, ag); ag = fmaf(g[3], a.w, ag);
        ag = fmaf(g[4], b.x, ag); ag = fmaf(g[5], b.y, ag);
        ag = fmaf(g[6], b.z, ag); ag = fmaf(g[7], b.w, ag);
        out[dstg] = ag;
    }
}

// ---------------------------------------------------------------------------
extern "C" void kernel_launch(void* const* d_in, const int* in_sizes, int n_in,
                              void* d_out, int out_size) {
    const float* T      = (const float*)d_in[0];
    const float* l      = (const float*)d_in[1];
    const float* ldot   = (const float*)d_in[2];
    const float* center = (const float*)d_in[3];
    const float* w1_1   = (const float*)d_in[4];
    const float* b1_1   = (const float*)d_in[5];
    const float* w2_1   = (const float*)d_in[6];
    const float* b2_1   = (const float*)d_in[7];
    const float* w1_2   = (const float*)d_in[8];
    const float* b1_2   = (const float*)d_in[9];
    const float* w2_2   = (const float*)d_in[10];
    const float* b2_2   = (const float*)d_in[11];
    const float* w_out  = (const float*)d_in[12];
    float* out = (float*)d_out;

    kPrepQA<<<H1, 128>>>(w1_1, b1_1, w2_1, b2_1, w1_2, b1_2, w2_2, b2_2);
    kS<<<NMON, 256>>>(w_out);
    kMain<<<ROWS_TOTAL / 256, 256>>>(T, l, ldot, center, out);
}

// round 12
// speedup vs baseline: 2.8093x; 1.1623x over previous
#include <cuda_runtime.h>
#include <cuda_bf16.h>
#include <cstdint>

// ---------------------------------------------------------------------------
// Net_58712202936903: 2-layer multiplicative net + JVP as a 45x45 quadratic
// form in the 8-dim monomial basis m(x) = (1, x_i, x_i x_j | i<=j).
//   out(x)     = 0.5 * m . (Ssym m)        (grad rows: full Ssym)
//   out(x)     = m . (S2 m)                (value rows: upper triangle S2)
//   grad(x,xd) = (J_m^T (Ssym m)) . xd
// ---------------------------------------------------------------------------

#define N_IN   8
#define H1     128
#define H2     128
#define NMON   45
#define SPAD   48      // padded row stride (12 float4)
#define NPAIR  36
#define QSTR   64      // Q smem row stride

#define ROWS_T 65536
#define ROWS_L 65536
#define ROWS_C 512
#define ROWS_TOTAL (ROWS_T + ROWS_L + ROWS_C)   // 131584 = 514*256

// pair index t -> (i,j), i<=j, row-major upper triangle of 8x8 (fold to
// immediates in fully unrolled loops).
__host__ __device__ constexpr int pair_i(int t) {
    int i = 0, off = 0;
    while (t >= off + (N_IN - i)) { off += N_IN - i; ++i; }
    return i;
}
__host__ __device__ constexpr int pair_j(int t) {
    int i = 0, off = 0;
    while (t >= off + (N_IN - i)) { off += N_IN - i; ++i; }
    return i + (t - off);
}

// device scratch (zero-initialized; entries never written stay 0 forever)
__device__ float gA1[H2 * SPAD];
__device__ float gA2[H2 * SPAD];
__device__ float gS [NMON * SPAD];   // full symmetric
__device__ float gS2[NMON * SPAD];   // upper triangle, diag halved, lower 0
__device__ unsigned int gTicket;     // monotone grid-barrier counter

// ---- packed f32x2 helpers --------------------------------------------------
__device__ __forceinline__ uint32_t smem_u32(const void* p) {
    uint32_t a;
    asm("{ .reg .u64 t; cvta.to.shared.u64 t, %1; cvt.u32.u64 %0, t; }"
        : "=r"(a) : "l"(p));
    return a;
}
#define FMA2(acc, a, b) \
    asm("fma.rn.f32x2 %0, %1, %2, %0;" : "+l"(acc) : "l"(a), "l"(b))
#define ADD2(d, a, b) \
    asm("add.rn.f32x2 %0, %1, %2;" : "=l"(d) : "l"(a), "l"(b))
#define PACK2(d, lo, hi) \
    asm("mov.b64 %0, {%1, %2};" : "=l"(d) : "f"(lo), "f"(hi))
#define UNPACK2(lo, hi, s) \
    asm("mov.b64 {%0, %1}, %2;" : "=f"(lo), "=f"(hi) : "l"(s))
#define LDS_V2B64(a, b, addr) \
    asm volatile("ld.shared.v2.b64 {%0, %1}, [%2];" \
                 : "=l"(a), "=l"(b) : "r"(addr))

// ---------------------------------------------------------------------------
// Fused prep: grid = 128 blocks x 128 threads.
//  Stage A (all blocks): block h computes A1[h,:], A2[h,:]   (Q built in smem)
//  grid barrier (ticket counter; 128 blocks co-resident on 148 SMs)
//  Stage B (blocks 0..44): block p computes Ssym[p,:] and S2[p,:]
// ---------------------------------------------------------------------------
__global__ void __launch_bounds__(128)
kPrep(const float* __restrict__ w1_1, const float* __restrict__ b1_1,
      const float* __restrict__ w2_1, const float* __restrict__ b2_1,
      const float* __restrict__ w1_2, const float* __restrict__ b1_2,
      const float* __restrict__ w2_2, const float* __restrict__ b2_2,
      const float* __restrict__ w_out) {
    __shared__ float sQ[H1 * QSTR];          // 32 KB
    __shared__ float sW1[H1], sW2[H1];
    __shared__ float pA1[2][QSTR], pA2[2][QSTR];
    __shared__ unsigned int sTarget;
    int tid = threadIdx.x;
    int h   = blockIdx.x;                    // 0..127

    // ---- Stage A phase 1: thread t builds Q row t (redundant per block) ----
    {
        int hr = tid;
        float a[N_IN], c[N_IN];
#pragma unroll
        for (int i = 0; i < N_IN; i++) { a[i] = w1_1[hr*N_IN+i]; c[i] = w2_1[hr*N_IN+i]; }
        float bb1 = b1_1[hr], bb2 = b2_1[hr];
        float* q = sQ + hr * QSTR;
        q[0] = bb1 * bb2;
#pragma unroll
        for (int i = 0; i < N_IN; i++) q[1+i] = fmaf(bb1, c[i], bb2 * a[i]);
#pragma unroll
        for (int t = 0; t < NPAIR; t++) {
            int i = pair_i(t), j = pair_j(t);
            q[9+t] = (i == j) ? a[i]*c[i] : fmaf(a[i], c[j], a[j]*c[i]);
        }
#pragma unroll
        for (int t = NMON; t < QSTR; t++) q[t] = 0.f;
        sW1[tid] = w1_2[h * H1 + tid];
        sW2[tid] = w2_2[h * H1 + tid];
    }
    __syncthreads();

    // ---- Stage A phase 2: half = o-range, p = column ----
    {
        int half = tid >> 6;                 // 0 or 1
        int p    = tid & 63;
        int obase = half * 64;
        float a1 = 0.f, a2 = 0.f;
#pragma unroll 8
        for (int oo = 0; oo < 64; oo++) {
            int o = obase + oo;
            float q = sQ[o * QSTR + p];
            a1 = fmaf(sW1[o], q, a1);
            a2 = fmaf(sW2[o], q, a2);
        }
        pA1[half][p] = a1;
        pA2[half][p] = a2;
    }
    __syncthreads();
    if (tid < NMON) {
        float r1 = pA1[0][tid] + pA1[1][tid];
        float r2 = pA2[0][tid] + pA2[1][tid];
        if (tid == 0) { r1 += b1_2[h]; r2 += b2_2[h]; }
        gA1[h * SPAD + tid] = r1;
        gA2[h * SPAD + tid] = r2;
        __threadfence();                     // make gA globally visible
    }
    __syncthreads();

    // ---- grid barrier: monotone ticket counter (graph-replay safe) ----
    if (tid == 0) {
        unsigned t = atomicAdd(&gTicket, 1u);
        sTarget = (t / 128u + 1u) * 128u;    // end of this launch's epoch
    }
    __syncthreads();
    if (h >= NMON) return;                   // blocks 45..127 done

    if (tid == 0) {
        unsigned target = sTarget;
        while (atomicAdd(&gTicket, 0u) < target) { }
        __threadfence();                     // acquire
    }
    __syncthreads();

    // ---- Stage B: block p computes Ssym row p ----
    {
        int p  = h;
        int hc = tid >> 6;                   // 0 or 1 (h-chunk)
        int q  = tid & 63;
        __shared__ float su1[H2], su2[H2], spp[2][QSTR];
        {
            float w = w_out[tid];
            su1[tid] = w * gA1[tid * SPAD + p];
            su2[tid] = w * gA2[tid * SPAD + p];
        }
        __syncthreads();
        float s0 = 0.f, s1 = 0.f;
        int hb = hc * 64;
#pragma unroll 8
        for (int hh = 0; hh < 64; hh += 2) {
            int hx = hb + hh;
            s0 = fmaf(su1[hx  ], gA2[(hx  )*SPAD+q], fmaf(su2[hx  ], gA1[(hx  )*SPAD+q], s0));
            s1 = fmaf(su1[hx+1], gA2[(hx+1)*SPAD+q], fmaf(su2[hx+1], gA1[(hx+1)*SPAD+q], s1));
        }
        spp[hc][q] = s0 + s1;
        __syncthreads();
        if (tid < NMON) {
            float ss = spp[0][tid] + spp[1][tid];
            gS[p * SPAD + tid] = ss;
            if (tid > p)       gS2[p * SPAD + tid] = ss;
            else if (tid == p) gS2[p * SPAD + tid] = 0.5f * ss;
            // tid < p: never written -> stays 0
        }
    }
}

// ---------------------------------------------------------------------------
// Main: one thread per row. Value blocks use triangle S2 (43% fewer FMA2);
// grad blocks use full Ssym. Block copies only the matrix it needs to smem.
// ---------------------------------------------------------------------------
__global__ void __launch_bounds__(256, 2)
kMain(const float* __restrict__ T, const float* __restrict__ L,
      const float* __restrict__ Ld, const float* __restrict__ C,
      float* __restrict__ out) {
    __shared__ __align__(16) float sS[NMON * SPAD];   // 8640 B
    int r = blockIdx.x * 256 + threadIdx.x;           // grid covers ROWS_TOTAL
    bool gradPath = (blockIdx.x >= 256) && (blockIdx.x < 512);   // L region

    {
        const float* srcS = gradPath ? gS : gS2;
        for (int i = threadIdx.x; i < NMON * SPAD; i += 256) sS[i] = srcS[i];
    }
    __syncthreads();
    uint32_t sbase = smem_u32(sS);

    float x[N_IN];
    int dsto, dstg = -1;
    const float* src;
    if (r < ROWS_T) {                        // value rows (T)
        src = T + (size_t)r * N_IN;
        dsto = r;
    } else if (r < ROWS_T + ROWS_L) {        // grad rows (L)
        int i = r - ROWS_T;
        src = L + (size_t)i * N_IN;
        dsto = ROWS_T + i;                   // v_y
        dstg = 2 * ROWS_T + i;               // v_grad
    } else {                                 // value rows (center)
        int i = r - (ROWS_T + ROWS_L);
        src = C + (size_t)i * N_IN;
        dsto = 3 * ROWS_T + i;               // v_center
    }
    {
        const float4* p4 = reinterpret_cast<const float4*>(src);
        float4 a = p4[0], b = p4[1];
        x[0]=a.x; x[1]=a.y; x[2]=a.z; x[3]=a.w;
        x[4]=b.x; x[5]=b.y; x[6]=b.z; x[7]=b.w;
    }

    // monomials packed into 24 f32x2 pairs
    float m[SPAD];
    m[0] = 1.f;
#pragma unroll
    for (int i = 0; i < N_IN; i++) m[1+i] = x[i];
#pragma unroll
    for (int t = 0; t < NPAIR; t++) m[9+t] = x[pair_i(t)] * x[pair_j(t)];
    m[45] = 0.f; m[46] = 0.f; m[47] = 0.f;
    unsigned long long mm[24];
#pragma unroll
    for (int k = 0; k < 24; k++) PACK2(mm[k], m[2*k], m[2*k+1]);

    if (!gradPath) {
        // ---- value path: out = m . (S2 m), rows start at aligned 4*floor(p/4)
        float acc = 0.f;
#pragma unroll
        for (int p = 0; p < NMON; p++) {
            const int qa = (p >> 2) << 2;
            const int nc = 12 - (p >> 2);    // float4 chunks in this row
            unsigned long long a0 = 0ull, a1 = 0ull;
#pragma unroll
            for (int c = 0; c < nc; c++) {
                unsigned long long ra, rb;
                LDS_V2B64(ra, rb, sbase + (uint32_t)((p * SPAD + qa + 4*c) * 4));
                FMA2(a0, ra, mm[(qa >> 1) + 2*c]);
                FMA2(a1, rb, mm[(qa >> 1) + 2*c + 1]);
            }
            unsigned long long tt;
            ADD2(tt, a0, a1);
            float va, vb;
            UNPACK2(va, vb, tt);
            float v = va + vb;
            if (p == 0) acc += v;
            else if (p < 9) acc = fmaf(x[p-1], v, acc);
            else {
                int i = pair_i(p - 9), j = pair_j(p - 9);
                acc = fmaf(x[i] * x[j], v, acc);
            }
        }
        out[dsto] = acc;
    } else {
        // ---- grad path: full Ssym, value + J^T v
        float acc_o = 0.f;
        float g[N_IN];
#pragma unroll
        for (int i = 0; i < N_IN; i++) g[i] = 0.f;

#pragma unroll
        for (int p = 0; p < NMON; p++) {
            unsigned long long a0 = 0ull, a1 = 0ull, a2 = 0ull, a3 = 0ull;
#pragma unroll
            for (int qq = 0; qq < 12; qq += 2) {
                unsigned long long ra, rb, rc, rd;
                LDS_V2B64(ra, rb, sbase + (uint32_t)((p * SPAD + qq * 4) * 4));
                LDS_V2B64(rc, rd, sbase + (uint32_t)((p * SPAD + qq * 4 + 4) * 4));
                FMA2(a0, ra, mm[2*qq+0]);
                FMA2(a1, rb, mm[2*qq+1]);
                FMA2(a2, rc, mm[2*qq+2]);
                FMA2(a3, rd, mm[2*qq+3]);
            }
            unsigned long long t0, t1, tt;
            ADD2(t0, a0, a1);
            ADD2(t1, a2, a3);
            ADD2(tt, t0, t1);
            float va, vb;
            UNPACK2(va, vb, tt);
            float v = va + vb;                // v_p = (Ssym m)_p
            if (p == 0) {
                acc_o += v;
            } else if (p < 9) {
                acc_o = fmaf(x[p-1], v, acc_o);
                g[p-1] += v;
            } else {
                int i = pair_i(p - 9), j = pair_j(p - 9);
                acc_o = fmaf(x[i] * x[j], v, acc_o);
                g[i] = fmaf(v, x[j], g[i]);
                g[j] = fmaf(v, x[i], g[j]);   // i==j double-add = 2 x_i v
            }
        }
        out[dsto] = 0.5f * acc_o;
        int i = r - ROWS_T;
        const float4* d4 = reinterpret_cast<const float4*>(Ld + (size_t)i * N_IN);
        float4 a = d4[0], b = d4[1];
        float ag = 0.f;
        ag = fmaf(g[0], a.x, ag); ag = fmaf(g[1], a.y, ag);
        ag = fmaf(g[2], a.z, ag); ag = fmaf(g[3], a.w, ag);
        ag = fmaf(g[4], b.x, ag); ag = fmaf(g[5], b.y, ag);
        ag = fmaf(g[6], b.z, ag); ag = fmaf(g[7], b.w, ag);
        out[dstg] = ag;
    }
}

// ---------------------------------------------------------------------------
extern "C" void kernel_launch(void* const* d_in, const int* in_sizes, int n_in,
                              void* d_out, int out_size) {
    const float* T      = (const float*)d_in[0];
    const float* l      = (const float*)d_in[1];
    const float* ldot   = (const float*)d_in[2];
    const float* center = (const float*)d_in[3];
    const float* w1_1   = (const float*)d_in[4];
    const float* b1_1   = (const float*)d_in[5];
    const float* w2_1   = (const float*)d_in[6];
    const float* b2_1   = (const float*)d_in[7];
    const float* w1_2   = (const float*)d_in[8];
    const float* b1_2   = (const float*)d_in[9];
    const float* w2_2   = (const float*)d_in[10];
    const float* b2_2   = (const float*)d_in[11];
    const float* w_out  = (const float*)d_in[12];
    float* out = (float*)d_out;

    kPrep<<<H1, 128>>>(w1_1, b1_1, w2_1, b2_1, w1_2, b1_2, w2_2, b2_2, w_out);
    kMain<<<ROWS_TOTAL / 256, 256>>>(T, l, ldot, center, out);
}

// round 16
// speedup vs baseline: 3.7991x; 1.3524x over previous
#include <cuda_runtime.h>
#include <cuda_bf16.h>
#include <cstdint>

// ---------------------------------------------------------------------------
// Net_58712202936903: 2-layer multiplicative net + JVP as a 45x45 quadratic
// form in the 8-dim monomial basis m(x) = (1, x_i, x_i x_j | i<=j).
//   value rows: out = m . (S2 m)            (S2 = upper triangle, diag/2)
//   grad rows:  out = 0.5 m . (Ssym m);  grad = (J_m^T (Ssym m)) . xd
// kMain is fully straight-line: templated rows, immediate-offset LDS,
// packed f32x2 FMA.
// ---------------------------------------------------------------------------

#define N_IN   8
#define H1     128
#define H2     128
#define NMON   45
#define SPAD   48      // padded row stride (12 float4)
#define NPAIR  36
#define QSTR   64      // Q smem row stride

#define ROWS_T 65536
#define ROWS_L 65536
#define ROWS_C 512
#define ROWS_TOTAL (ROWS_T + ROWS_L + ROWS_C)   // 131584 = 514*256

__host__ __device__ constexpr int pair_i(int t) {
    int i = 0, off = 0;
    while (t >= off + (N_IN - i)) { off += N_IN - i; ++i; }
    return i;
}
__host__ __device__ constexpr int pair_j(int t) {
    int i = 0, off = 0;
    while (t >= off + (N_IN - i)) { off += N_IN - i; ++i; }
    return i + (t - off);
}

// device scratch (zero-initialized; entries never written stay 0 forever)
__device__ float gA1[H2 * SPAD];
__device__ float gA2[H2 * SPAD];
__device__ float gS [NMON * SPAD];   // full symmetric
__device__ float gS2[NMON * SPAD];   // upper triangle, diag halved, lower 0
__device__ unsigned int gTicket;     // monotone grid-barrier counter

// ---- packed f32x2 helpers --------------------------------------------------
__device__ __forceinline__ uint32_t smem_u32(const void* p) {
    uint32_t a;
    asm("{ .reg .u64 t; cvta.to.shared.u64 t, %1; cvt.u32.u64 %0, t; }"
        : "=r"(a) : "l"(p));
    return a;
}
#define FMA2(acc, a, b) \
    asm("fma.rn.f32x2 %0, %1, %2, %0;" : "+l"(acc) : "l"(a), "l"(b))
#define ADD2(d, a, b) \
    asm("add.rn.f32x2 %0, %1, %2;" : "=l"(d) : "l"(a), "l"(b))
#define PACK2(d, lo, hi) \
    asm("mov.b64 %0, {%1, %2};" : "=l"(d) : "f"(lo), "f"(hi))
#define UNPACK2(lo, hi, s) \
    asm("mov.b64 {%0, %1}, %2;" : "=f"(lo), "=f"(hi) : "l"(s))

// LDS.128 with compile-time immediate offset: single base register, no IADD3.
template<int OFF>
__device__ __forceinline__ void lds2(uint32_t base, unsigned long long& a,
                                     unsigned long long& b) {
    asm volatile("ld.shared.v2.b64 {%0, %1}, [%2+%3];"
                 : "=l"(a), "=l"(b) : "r"(base), "n"(OFF));
}

// ---------------------------------------------------------------------------
// Straight-line matvec machinery (all offsets/indices compile-time)
// ---------------------------------------------------------------------------
// Value path: row P of S2 has nonzeros only in chunks [(P>>2) .. 11]
template<int P, int C, int NC>
struct ChunkV {
    static __device__ __forceinline__ void run(uint32_t sbase,
            const unsigned long long (&mm)[24],
            unsigned long long& a0, unsigned long long& a1) {
        constexpr int QA  = (P >> 2) << 2;
        constexpr int OFF = (P * SPAD + QA + 4 * C) * 4;
        unsigned long long ra, rb;
        lds2<OFF>(sbase, ra, rb);
        FMA2(a0, ra, mm[(QA >> 1) + 2 * C]);
        FMA2(a1, rb, mm[(QA >> 1) + 2 * C + 1]);
        ChunkV<P, C + 1, NC>::run(sbase, mm, a0, a1);
    }
};
template<int P, int NC>
struct ChunkV<P, NC, NC> {
    static __device__ __forceinline__ void run(uint32_t,
            const unsigned long long (&)[24],
            unsigned long long&, unsigned long long&) {}
};

template<int P>
struct RowV {
    static __device__ __forceinline__ void run(uint32_t sbase,
            const unsigned long long (&mm)[24], const float (&x)[N_IN],
            float& acc) {
        constexpr int NC = 12 - (P >> 2);
        unsigned long long a0 = 0ull, a1 = 0ull;
        ChunkV<P, 0, NC>::run(sbase, mm, a0, a1);
        unsigned long long tt;
        ADD2(tt, a0, a1);
        float va, vb;
        UNPACK2(va, vb, tt);
        float v = va + vb;
        if constexpr (P == 0) {
            acc += v;
        } else if constexpr (P < 9) {
            acc = fmaf(x[P - 1], v, acc);
        } else {
            constexpr int i = pair_i(P - 9), j = pair_j(P - 9);
            acc = fmaf(x[i] * x[j], v, acc);
        }
        RowV<P + 1>::run(sbase, mm, x, acc);
    }
};
template<>
struct RowV<NMON> {
    static __device__ __forceinline__ void run(uint32_t,
            const unsigned long long (&)[24], const float (&)[N_IN], float&) {}
};

// Grad path: full rows (12 chunks), 4 accumulators
template<int P, int C>
struct ChunkG {
    static __device__ __forceinline__ void run(uint32_t sbase,
            const unsigned long long (&mm)[24],
            unsigned long long& a0, unsigned long long& a1,
            unsigned long long& a2, unsigned long long& a3) {
        constexpr int OFF = (P * SPAD + 4 * C) * 4;
        unsigned long long ra, rb;
        lds2<OFF>(sbase, ra, rb);
        if constexpr ((C & 1) == 0) {
            FMA2(a0, ra, mm[2 * C]);
            FMA2(a1, rb, mm[2 * C + 1]);
        } else {
            FMA2(a2, ra, mm[2 * C]);
            FMA2(a3, rb, mm[2 * C + 1]);
        }
        ChunkG<P, C + 1>::run(sbase, mm, a0, a1, a2, a3);
    }
};
template<int P>
struct ChunkG<P, 12> {
    static __device__ __forceinline__ void run(uint32_t,
            const unsigned long long (&)[24],
            unsigned long long&, unsigned long long&,
            unsigned long long&, unsigned long long&) {}
};

template<int P>
struct RowG {
    static __device__ __forceinline__ void run(uint32_t sbase,
            const unsigned long long (&mm)[24], const float (&x)[N_IN],
            float& acc_o, float (&g)[N_IN]) {
        unsigned long long a0 = 0ull, a1 = 0ull, a2 = 0ull, a3 = 0ull;
        ChunkG<P, 0>::run(sbase, mm, a0, a1, a2, a3);
        unsigned long long t0, t1, tt;
        ADD2(t0, a0, a1);
        ADD2(t1, a2, a3);
        ADD2(tt, t0, t1);
        float va, vb;
        UNPACK2(va, vb, tt);
        float v = va + vb;                    // v_p = (Ssym m)_p
        if constexpr (P == 0) {
            acc_o += v;
        } else if constexpr (P < 9) {
            acc_o = fmaf(x[P - 1], v, acc_o);
            g[P - 1] += v;
        } else {
            constexpr int i = pair_i(P - 9), j = pair_j(P - 9);
            acc_o = fmaf(x[i] * x[j], v, acc_o);
            g[i] = fmaf(v, x[j], g[i]);
            g[j] = fmaf(v, x[i], g[j]);       // i==j double-add = 2 x_i v
        }
        RowG<P + 1>::run(sbase, mm, x, acc_o, g);
    }
};
template<>
struct RowG<NMON> {
    static __device__ __forceinline__ void run(uint32_t,
            const unsigned long long (&)[24], const float (&)[N_IN],
            float&, float (&)[N_IN]) {}
};

// ---------------------------------------------------------------------------
// Fused prep: grid = 128 blocks x 128 threads.
//  Stage A (all blocks): block h computes A1[h,:], A2[h,:]
//  grid barrier (monotone ticket; 128 blocks co-resident on 148 SMs)
//  Stage B (blocks 0..44): block p computes Ssym[p,:] and S2[p,:]
// ---------------------------------------------------------------------------
__global__ void __launch_bounds__(128)
kPrep(const float* __restrict__ w1_1, const float* __restrict__ b1_1,
      const float* __restrict__ w2_1, const float* __restrict__ b2_1,
      const float* __restrict__ w1_2, const float* __restrict__ b1_2,
      const float* __restrict__ w2_2, const float* __restrict__ b2_2,
      const float* __restrict__ w_out) {
    __shared__ float sQ[H1 * QSTR];          // 32 KB
    __shared__ float sW1[H1], sW2[H1];
    __shared__ float pA1[2][QSTR], pA2[2][QSTR];
    __shared__ unsigned int sTarget;
    int tid = threadIdx.x;
    int h   = blockIdx.x;                    // 0..127

    // ---- Stage A phase 1: thread t builds Q row t (redundant per block) ----
    {
        int hr = tid;
        float a[N_IN], c[N_IN];
#pragma unroll
        for (int i = 0; i < N_IN; i++) { a[i] = w1_1[hr*N_IN+i]; c[i] = w2_1[hr*N_IN+i]; }
        float bb1 = b1_1[hr], bb2 = b2_1[hr];
        float* q = sQ + hr * QSTR;
        q[0] = bb1 * bb2;
#pragma unroll
        for (int i = 0; i < N_IN; i++) q[1+i] = fmaf(bb1, c[i], bb2 * a[i]);
#pragma unroll
        for (int t = 0; t < NPAIR; t++) {
            int i = pair_i(t), j = pair_j(t);
            q[9+t] = (i == j) ? a[i]*c[i] : fmaf(a[i], c[j], a[j]*c[i]);
        }
#pragma unroll
        for (int t = NMON; t < QSTR; t++) q[t] = 0.f;
        sW1[tid] = w1_2[h * H1 + tid];
        sW2[tid] = w2_2[h * H1 + tid];
    }
    __syncthreads();

    // ---- Stage A phase 2 ----
    {
        int half = tid >> 6;
        int p    = tid & 63;
        int obase = half * 64;
        float a1 = 0.f, a2 = 0.f;
#pragma unroll 8
        for (int oo = 0; oo < 64; oo++) {
            int o = obase + oo;
            float q = sQ[o * QSTR + p];
            a1 = fmaf(sW1[o], q, a1);
            a2 = fmaf(sW2[o], q, a2);
        }
        pA1[half][p] = a1;
        pA2[half][p] = a2;
    }
    __syncthreads();
    if (tid < NMON) {
        float r1 = pA1[0][tid] + pA1[1][tid];
        float r2 = pA2[0][tid] + pA2[1][tid];
        if (tid == 0) { r1 += b1_2[h]; r2 += b2_2[h]; }
        gA1[h * SPAD + tid] = r1;
        gA2[h * SPAD + tid] = r2;
        __threadfence();
    }
    __syncthreads();

    // ---- grid barrier ----
    if (tid == 0) {
        unsigned t = atomicAdd(&gTicket, 1u);
        sTarget = (t / 128u + 1u) * 128u;
    }
    __syncthreads();
    if (h >= NMON) return;

    if (tid == 0) {
        unsigned target = sTarget;
        while (atomicAdd(&gTicket, 0u) < target) { }
        __threadfence();
    }
    __syncthreads();

    // ---- Stage B ----
    {
        int p  = h;
        int hc = tid >> 6;
        int q  = tid & 63;
        __shared__ float su1[H2], su2[H2], spp[2][QSTR];
        {
            float w = w_out[tid];
            su1[tid] = w * gA1[tid * SPAD + p];
            su2[tid] = w * gA2[tid * SPAD + p];
        }
        __syncthreads();
        float s0 = 0.f, s1 = 0.f;
        int hb = hc * 64;
#pragma unroll 8
        for (int hh = 0; hh < 64; hh += 2) {
            int hx = hb + hh;
            s0 = fmaf(su1[hx  ], gA2[(hx  )*SPAD+q], fmaf(su2[hx  ], gA1[(hx  )*SPAD+q], s0));
            s1 = fmaf(su1[hx+1], gA2[(hx+1)*SPAD+q], fmaf(su2[hx+1], gA1[(hx+1)*SPAD+q], s1));
        }
        spp[hc][q] = s0 + s1;
        __syncthreads();
        if (tid < NMON) {
            float ss = spp[0][tid] + spp[1][tid];
            gS[p * SPAD + tid] = ss;
            if (tid > p)       gS2[p * SPAD + tid] = ss;
            else if (tid == p) gS2[p * SPAD + tid] = 0.5f * ss;
        }
    }
}

// ---------------------------------------------------------------------------
// Main: one thread per row; fully straight-line matvec.
// ---------------------------------------------------------------------------
__global__ void __launch_bounds__(256, 2)
kMain(const float* __restrict__ T, const float* __restrict__ L,
      const float* __restrict__ Ld, const float* __restrict__ C,
      float* __restrict__ out) {
    __shared__ __align__(16) float sS[NMON * SPAD];   // 8640 B
    int r = blockIdx.x * 256 + threadIdx.x;
    bool gradPath = (blockIdx.x >= 256) && (blockIdx.x < 512);

    {
        const float* srcS = gradPath ? gS : gS2;
        for (int i = threadIdx.x; i < NMON * SPAD; i += 256) sS[i] = srcS[i];
    }
    __syncthreads();
    uint32_t sbase = smem_u32(sS);

    float x[N_IN];
    int dsto, dstg = -1;
    const float* src;
    if (r < ROWS_T) {
        src = T + (size_t)r * N_IN;
        dsto = r;
    } else if (r < ROWS_T + ROWS_L) {
        int i = r - ROWS_T;
        src = L + (size_t)i * N_IN;
        dsto = ROWS_T + i;                   // v_y
        dstg = 2 * ROWS_T + i;               // v_grad
    } else {
        int i = r - (ROWS_T + ROWS_L);
        src = C + (size_t)i * N_IN;
        dsto = 3 * ROWS_T + i;               // v_center
    }
    {
        const float4* p4 = reinterpret_cast<const float4*>(src);
        float4 a = p4[0], b = p4[1];
        x[0]=a.x; x[1]=a.y; x[2]=a.z; x[3]=a.w;
        x[4]=b.x; x[5]=b.y; x[6]=b.z; x[7]=b.w;
    }

    // monomials packed into 24 f32x2 pairs
    float m[SPAD];
    m[0] = 1.f;
#pragma unroll
    for (int i = 0; i < N_IN; i++) m[1+i] = x[i];
#pragma unroll
    for (int t = 0; t < NPAIR; t++) m[9+t] = x[pair_i(t)] * x[pair_j(t)];
    m[45] = 0.f; m[46] = 0.f; m[47] = 0.f;
    unsigned long long mm[24];
#pragma unroll
    for (int k = 0; k < 24; k++) PACK2(mm[k], m[2*k], m[2*k+1]);

    if (!gradPath) {
        float acc = 0.f;
        RowV<0>::run(sbase, mm, x, acc);
        out[dsto] = acc;
    } else {
        float acc_o = 0.f;
        float g[N_IN];
#pragma unroll
        for (int i = 0; i < N_IN; i++) g[i] = 0.f;
        RowG<0>::run(sbase, mm, x, acc_o, g);
        out[dsto] = 0.5f * acc_o;
        int i = r - ROWS_T;
        const float4* d4 = reinterpret_cast<const float4*>(Ld + (size_t)i * N_IN);
        float4 a = d4[0], b = d4[1];
        float ag = 0.f;
        ag = fmaf(g[0], a.x, ag); ag = fmaf(g[1], a.y, ag);
        ag = fmaf(g[2], a.z, ag); ag = fmaf(g[3], a.w, ag);
        ag = fmaf(g[4], b.x, ag); ag = fmaf(g[5], b.y, ag);
        ag = fmaf(g[6], b.z, ag); ag = fmaf(g[7], b.w, ag);
        out[dstg] = ag;
    }
}

// ---------------------------------------------------------------------------
extern "C" void kernel_launch(void* const* d_in, const int* in_sizes, int n_in,
                              void* d_out, int out_size) {
    const float* T      = (const float*)d_in[0];
    const float* l      = (const float*)d_in[1];
    const float* ldot   = (const float*)d_in[2];
    const float* center = (const float*)d_in[3];
    const float* w1_1   = (const float*)d_in[4];
    const float* b1_1   = (const float*)d_in[5];
    const float* w2_1   = (const float*)d_in[6];
    const float* b2_1   = (const float*)d_in[7];
    const float* w1_2   = (const float*)d_in[8];
    const float* b1_2   = (const float*)d_in[9];
    const float* w2_2   = (const float*)d_in[10];
    const float* b2_2   = (const float*)d_in[11];
    const float* w_out  = (const float*)d_in[12];
    float* out = (float*)d_out;

    kPrep<<<H1, 128>>>(w1_1, b1_1, w2_1, b2_1, w1_2, b1_2, w2_2, b2_2, w_out);
    kMain<<<ROWS_TOTAL / 256, 256>>>(T, l, ldot, center, out);
}